// round 4
// baseline (speedup 1.0000x reference)
#include <cuda_runtime.h>

// stepSSM fused kernel, R4: packed float4 shared constants (LDS.128 x5/layer
// instead of ~19 scalar LDS), 4 threads per row for fully coalesced state I/O.
//
// Shared layout: per (layer i, quad q): 5 float4 at scv[(i*4+q)*5]:
//   c0 = A [i, k..k+3]        (k = q*4 in flattened [2,4,2])
//   c1 = Bm[i, k..k+3]
//   c2 = C [i, k..k+3]
//   c3 = { D[i,hd], fc_w[i,0], fc_w[i,1], fc_b[i,0] }   (hd = q>>1)
//   c4 = { fc_w[i,2], fc_w[i,3], fc_b[i,1], 0 }
// Tail (broadcast): scv[80]=fc1_w[0..3], scv[81]=fc1_w[4..7],
//   scv[82]={fc1_b0,fc1_b1,-,-}, scv[83]={fcw16,fcw17,fcb8,-},
//   scv[84]={fcw18,fcw19,fcb9,-}.
// Bank math: q-stride = 20 words; per LDS.128 phase the 4 q's hit banks
// {0-3},{20-23},{8-11},{28-31} -> conflict-free broadcast.
//
// Inputs (metadata order):
//   0: x[B,4]  1: states[4,B,2,4,2]  2: fc1_w[2,4]  3: fc1_b[2]
//   4: fc_w[5,2,2]  5: fc_b[5,2]  6: A[4,2,4,2]  7: Bm[4,2,4,2]
//   8: C[4,1,2,4,2]  9: D[4,1,2]
// Output: h[B,2] ++ new_states[4,B,2,4,2]  (f32)

#define THREADS 256
#define N_V4 85

__global__ __launch_bounds__(THREADS) void step_ssm_kernel(
    const float4* __restrict__ x,        // [B]
    const float4* __restrict__ states,   // [4*B*4] float4
    const float*  __restrict__ fc1_w,
    const float*  __restrict__ fc1_b,
    const float*  __restrict__ fc_w,
    const float*  __restrict__ fc_b,
    const float*  __restrict__ A,
    const float*  __restrict__ Bm,
    const float*  __restrict__ C,
    const float*  __restrict__ D,
    float2*       __restrict__ out_h,      // [B]
    float4*       __restrict__ out_states, // [4*B*4] float4
    int B)
{
    __shared__ float4 scv[N_V4];
    {
        int t = threadIdx.x;
        if (t < 80) {
            int i = t / 20, rem = t % 20;
            int qq = rem / 5, c = rem % 5;
            int lb = i * 16 + qq * 4;
            float4 v;
            if      (c == 0) v = make_float4(A [lb], A [lb+1], A [lb+2], A [lb+3]);
            else if (c == 1) v = make_float4(Bm[lb], Bm[lb+1], Bm[lb+2], Bm[lb+3]);
            else if (c == 2) v = make_float4(C [lb], C [lb+1], C [lb+2], C [lb+3]);
            else if (c == 3) v = make_float4(D[i*2 + (qq>>1)], fc_w[i*4+0], fc_w[i*4+1], fc_b[i*2+0]);
            else             v = make_float4(fc_w[i*4+2], fc_w[i*4+3], fc_b[i*2+1], 0.0f);
            scv[t] = v;
        } else if (t < N_V4) {
            float4 v;
            if      (t == 80) v = make_float4(fc1_w[0], fc1_w[1], fc1_w[2], fc1_w[3]);
            else if (t == 81) v = make_float4(fc1_w[4], fc1_w[5], fc1_w[6], fc1_w[7]);
            else if (t == 82) v = make_float4(fc1_b[0], fc1_b[1], 0.0f, 0.0f);
            else if (t == 83) v = make_float4(fc_w[16], fc_w[17], fc_b[8], 0.0f);
            else              v = make_float4(fc_w[18], fc_w[19], fc_b[9], 0.0f);
            scv[t] = v;
        }
    }
    __syncthreads();

    const int t   = blockIdx.x * blockDim.x + threadIdx.x;
    const int row = t >> 2;
    const int q   = t & 3;
    if (row >= B) return;

    const size_t layer_str = (size_t)B * 4;   // float4 units
    const size_t my_off    = (size_t)row * 4 + q;

    // front-load all global reads (MLP=5)
    float4 st[4];
#pragma unroll
    for (int i = 0; i < 4; i++)
        st[i] = __ldcs(states + (size_t)i * layer_str + my_off);
    float4 xv = __ldg(x + row);

    // fc1 (replicated across the quad)
    float4 w0 = scv[80], w1 = scv[81], bb = scv[82];
    float h0 = fmaf(xv.x, w0.x, fmaf(xv.y, w0.y, fmaf(xv.z, w0.z, fmaf(xv.w, w0.w, bb.x))));
    float h1 = fmaf(xv.x, w1.x, fmaf(xv.y, w1.y, fmaf(xv.z, w1.z, fmaf(xv.w, w1.w, bb.y))));

    const int hd = q >> 1;

#pragma unroll
    for (int i = 0; i < 4; i++) {
        const int base = (i * 4 + q) * 5;
        float4 a  = scv[base + 0];
        float4 b  = scv[base + 1];
        float4 c  = scv[base + 2];
        float4 d3 = scv[base + 3];
        float4 d4 = scv[base + 4];

        const float u = (hd == 0) ? h0 : h1;

        float nr0 = fmaf(a.x, st[i].x, fmaf(-a.y, st[i].y, b.x * u));
        float ni0 = fmaf(a.x, st[i].y, fmaf( a.y, st[i].x, b.y * u));
        float nr1 = fmaf(a.z, st[i].z, fmaf(-a.w, st[i].w, b.z * u));
        float ni1 = fmaf(a.z, st[i].w, fmaf( a.w, st[i].z, b.w * u));

        __stcs(out_states + (size_t)i * layer_str + my_off,
               make_float4(nr0, ni0, nr1, ni1));

        float acc = fmaf(c.x, nr0, fmaf(-c.y, ni0,
                    fmaf(c.z, nr1, -c.w * ni1)));
        acc += __shfl_xor_sync(0xFFFFFFFFu, acc, 1);

        float y = fmaf(2.0f, acc, u * d3.x);
        y = (y >= 0.0f) ? y : 0.125f * y;
        float yo = __shfl_xor_sync(0xFFFFFFFFu, y, 2);
        float y0 = (hd == 0) ? y  : yo;
        float y1 = (hd == 0) ? yo : y;

        h0 = fmaf(y0, d3.y, fmaf(y1, d3.z, d3.w));
        h1 = fmaf(y0, d4.x, fmaf(y1, d4.y, d4.z));
    }

    // fc10 — lane q==0 of each quad writes the contiguous float2
    if (q == 0) {
        float4 p0 = scv[83], p1 = scv[84];
        float o0 = fmaf(h0, p0.x, fmaf(h1, p0.y, p0.z));
        float o1 = fmaf(h0, p1.x, fmaf(h1, p1.y, p1.z));
        out_h[row] = make_float2(o0, o1);
    }
}

extern "C" void kernel_launch(void* const* d_in, const int* in_sizes, int n_in,
                              void* d_out, int out_size)
{
    const float* x     = (const float*)d_in[0];
    const float* states= (const float*)d_in[1];
    const float* fc1_w = (const float*)d_in[2];
    const float* fc1_b = (const float*)d_in[3];
    const float* fc_w  = (const float*)d_in[4];
    const float* fc_b  = (const float*)d_in[5];
    const float* A     = (const float*)d_in[6];
    const float* Bm    = (const float*)d_in[7];
    const float* C     = (const float*)d_in[8];
    const float* D     = (const float*)d_in[9];

    int B = in_sizes[0] / 4;  // x is [B,4]

    float*  out = (float*)d_out;
    float2* oh  = (float2*)out;                   // h: [B,2]
    float4* ost = (float4*)(out + (size_t)2 * B); // new_states: [4,B,2,4,2]

    long long total = (long long)B * 4;           // 4 threads per row
    int grid = (int)((total + THREADS - 1) / THREADS);
    step_ssm_kernel<<<grid, THREADS>>>(
        (const float4*)x, (const float4*)states,
        fc1_w, fc1_b, fc_w, fc_b, A, Bm, C, D,
        oh, ost, B);
}

// round 6
// speedup vs baseline: 1.5191x; 1.5191x over previous
#include <cuda_runtime.h>

// stepSSM fused kernel, R5: R3 structure (4 threads/row, scalar smem consts,
// coalesced float4 state I/O) + algebraic chain-shortening.
//
// Key identity per layer/head:
//   y = 2*Sum_f Re(C * (A*s)) + u * (2*Sum_f Re(C*B) + D)
//     = 2*accS + u*e,   e = 2*kCB + D  (constant, computed at setup)
// => all state-dependent work (A*s, C-projection, both quad shfl reductions)
//    is u-independent and runs upfront for all 4 layers in parallel; the
//    sequential h-chain is just fma -> leaky -> 2x fma per layer (~20 cyc).
//    State writes ns = P + B*u branch off u immediately (not on the chain).
//
// Inputs (metadata order):
//   0: x[B,4]  1: states[4,B,2,4,2]  2: fc1_w[2,4]  3: fc1_b[2]
//   4: fc_w[5,2,2]  5: fc_b[5,2]  6: A[4,2,4,2]  7: Bm[4,2,4,2]
//   8: C[4,1,2,4,2]  9: D[4,1,2]
// Output: h[B,2] ++ new_states[4,B,2,4,2]  (f32)

#define THREADS 256

#define OFF_FC1W 0    // 8
#define OFF_FC1B 8    // 2
#define OFF_FCW  10   // 20
#define OFF_FCB  30   // 10
#define OFF_A    40   // 64
#define OFF_BM   104  // 64
#define OFF_C    168  // 64
#define OFF_E    232  // 8  : e[i*2+h] = 2*sum_f(Cr*Br - Ci*Bi) + D[i,h]
#define N_CONST  240

__global__ __launch_bounds__(THREADS) void step_ssm_kernel(
    const float4* __restrict__ x,        // [B]
    const float4* __restrict__ states,   // [4*B*4] float4
    const float*  __restrict__ fc1_w,
    const float*  __restrict__ fc1_b,
    const float*  __restrict__ fc_w,
    const float*  __restrict__ fc_b,
    const float*  __restrict__ A,
    const float*  __restrict__ Bm,
    const float*  __restrict__ C,
    const float*  __restrict__ D,
    float2*       __restrict__ out_h,      // [B]
    float4*       __restrict__ out_states, // [4*B*4] float4
    int B)
{
    __shared__ float sc[N_CONST];
    {
        int t = threadIdx.x;
        if (t < OFF_E) {
            float v;
            if      (t < OFF_FC1B) v = fc1_w[t - OFF_FC1W];
            else if (t < OFF_FCW)  v = fc1_b[t - OFF_FC1B];
            else if (t < OFF_FCB)  v = fc_w [t - OFF_FCW];
            else if (t < OFF_A)    v = fc_b [t - OFF_FCB];
            else if (t < OFF_BM)   v = A    [t - OFF_A];
            else if (t < OFF_C)    v = Bm   [t - OFF_BM];
            else                   v = C    [t - OFF_C];
            sc[t] = v;
        } else if (t < N_CONST) {
            int r = t - OFF_E;         // 0..7
            int i = r >> 1, hh = r & 1;
            float kcb = 0.0f;
            #pragma unroll
            for (int f = 0; f < 4; f++) {
                int idx = i * 16 + hh * 8 + f * 2;
                kcb += C[idx] * Bm[idx] - C[idx + 1] * Bm[idx + 1];
            }
            sc[t] = 2.0f * kcb + D[i * 2 + hh];
        }
    }
    __syncthreads();

    const int t   = blockIdx.x * blockDim.x + threadIdx.x;
    const int row = t >> 2;
    const int q   = t & 3;
    if (row >= B) return;

    const size_t layer_str = (size_t)B * 4;   // float4 units
    const size_t my_off    = (size_t)row * 4 + q;

    // ---- phase 1: all global reads up front ----
    float4 st[4];
#pragma unroll
    for (int i = 0; i < 4; i++)
        st[i] = __ldcs(states + (size_t)i * layer_str + my_off);
    float4 xv = __ldg(x + row);

    // fc1 (replicated across quad)
    float h0 = fmaf(xv.x, sc[OFF_FC1W + 0], fmaf(xv.y, sc[OFF_FC1W + 1],
               fmaf(xv.z, sc[OFF_FC1W + 2], fmaf(xv.w, sc[OFF_FC1W + 3], sc[OFF_FC1B + 0]))));
    float h1 = fmaf(xv.x, sc[OFF_FC1W + 4], fmaf(xv.y, sc[OFF_FC1W + 5],
               fmaf(xv.z, sc[OFF_FC1W + 6], fmaf(xv.w, sc[OFF_FC1W + 7], sc[OFF_FC1B + 1]))));

    const int  hd = q >> 1;
    const int  kq = q * 4;

    // ---- phase 2: u-independent precompute for all 4 layers ----
    // st[i] <- P (complex A*s); Breg kept for deferred ns = P + B*u;
    // acc2_0/1[i] = 2 * Sum_f Re(C * P) per head (both heads via 2 shfls,
    // all layers' shfls pipelined in parallel here, off the h-chain).
    float Br0[4], Bi0[4], Br1[4], Bi1[4];
    float acc2_0[4], acc2_1[4];
#pragma unroll
    for (int i = 0; i < 4; i++) {
        const int lb = i * 16 + kq;
        float Ar0 = sc[OFF_A + lb + 0], Ai0 = sc[OFF_A + lb + 1];
        float Ar1 = sc[OFF_A + lb + 2], Ai1 = sc[OFF_A + lb + 3];
        Br0[i] = sc[OFF_BM + lb + 0];  Bi0[i] = sc[OFF_BM + lb + 1];
        Br1[i] = sc[OFF_BM + lb + 2];  Bi1[i] = sc[OFF_BM + lb + 3];
        float Cr0 = sc[OFF_C + lb + 0], Ci0 = sc[OFF_C + lb + 1];
        float Cr1 = sc[OFF_C + lb + 2], Ci1 = sc[OFF_C + lb + 3];

        float Pr0 = Ar0 * st[i].x - Ai0 * st[i].y;
        float Pi0 = Ar0 * st[i].y + Ai0 * st[i].x;
        float Pr1 = Ar1 * st[i].z - Ai1 * st[i].w;
        float Pi1 = Ar1 * st[i].w + Ai1 * st[i].z;
        st[i] = make_float4(Pr0, Pi0, Pr1, Pi1);

        float accS = Cr0 * Pr0 - Ci0 * Pi0 + Cr1 * Pr1 - Ci1 * Pi1;
        accS += __shfl_xor_sync(0xFFFFFFFFu, accS, 1);   // sum over f within head
        float accO = __shfl_xor_sync(0xFFFFFFFFu, accS, 2); // other head's sum
        accS *= 2.0f;
        accO *= 2.0f;
        acc2_0[i] = (hd == 0) ? accS : accO;
        acc2_1[i] = (hd == 0) ? accO : accS;
    }

    // ---- phase 3: short sequential chain + early state stores ----
#pragma unroll
    for (int i = 0; i < 4; i++) {
        const float u = (hd == 0) ? h0 : h1;   // layer input for own head

        // deferred state write: ns = P + B*u (branches off u, not on chain)
        __stcs(out_states + (size_t)i * layer_str + my_off,
               make_float4(fmaf(Br0[i], u, st[i].x),
                           fmaf(Bi0[i], u, st[i].y),
                           fmaf(Br1[i], u, st[i].z),
                           fmaf(Bi1[i], u, st[i].w)));

        // y = 2*accS + u*e ; leaky(0.125) ; 2x2 fc
        float z0 = fmaf(h0, sc[OFF_E + i * 2 + 0], acc2_0[i]);
        float z1 = fmaf(h1, sc[OFF_E + i * 2 + 1], acc2_1[i]);
        float y0 = (z0 >= 0.0f) ? z0 : 0.125f * z0;
        float y1 = (z1 >= 0.0f) ? z1 : 0.125f * z1;

        const int wb = OFF_FCW + i * 4;
        h0 = fmaf(y0, sc[wb + 0], fmaf(y1, sc[wb + 1], sc[OFF_FCB + i * 2 + 0]));
        h1 = fmaf(y0, sc[wb + 2], fmaf(y1, sc[wb + 3], sc[OFF_FCB + i * 2 + 1]));
    }

    // fc10 — lane q==0 writes the contiguous float2
    if (q == 0) {
        const int wb = OFF_FCW + 16;
        float o0 = fmaf(h0, sc[wb + 0], fmaf(h1, sc[wb + 1], sc[OFF_FCB + 8]));
        float o1 = fmaf(h0, sc[wb + 2], fmaf(h1, sc[wb + 3], sc[OFF_FCB + 9]));
        out_h[row] = make_float2(o0, o1);
    }
}

extern "C" void kernel_launch(void* const* d_in, const int* in_sizes, int n_in,
                              void* d_out, int out_size)
{
    const float* x     = (const float*)d_in[0];
    const float* states= (const float*)d_in[1];
    const float* fc1_w = (const float*)d_in[2];
    const float* fc1_b = (const float*)d_in[3];
    const float* fc_w  = (const float*)d_in[4];
    const float* fc_b  = (const float*)d_in[5];
    const float* A     = (const float*)d_in[6];
    const float* Bm    = (const float*)d_in[7];
    const float* C     = (const float*)d_in[8];
    const float* D     = (const float*)d_in[9];

    int B = in_sizes[0] / 4;  // x is [B,4]

    float*  out = (float*)d_out;
    float2* oh  = (float2*)out;                   // h: [B,2]
    float4* ost = (float4*)(out + (size_t)2 * B); // new_states: [4,B,2,4,2]

    long long total = (long long)B * 4;           // 4 threads per row
    int grid = (int)((total + THREADS - 1) / THREADS);
    step_ssm_kernel<<<grid, THREADS>>>(
        (const float4*)x, (const float4*)states,
        fc1_w, fc1_b, fc_w, fc_b, A, Bm, C, D,
        oh, ost, B);
}